// round 7
// baseline (speedup 1.0000x reference)
#include <cuda_runtime.h>
#include <math.h>

#define M_ANCH   589824
#define NCLS     80
#define K_TOP    1000
#define CAND_CAP 4096
#define NBINS    2048
#define GRID     576
#define NTHR     256
#define CHUNK_ROWS 256
#define NCHUNKS  (M_ANCH / CHUNK_ROWS)   /* 2304 */
#define NBAR_FINAL 5
#define IMG_INV  (1.0f/2048.0f)
#define SCALE_CLAMP 4.1351665567423560f   /* log(1000/16) */

// ---------------- scratch (device globals; no allocations allowed) ----------
__device__ unsigned            g_key[M_ANCH];
__device__ unsigned            g_hist1[NBINS];
__device__ unsigned            g_hist2[NBINS];
__device__ unsigned            g_candCount;
__device__ unsigned long long  g_cand[CAND_CAP];
__device__ float4              g_boxes[K_TOP];
__device__ int                 g_labels[K_TOP];
__device__ unsigned            g_validw[32];     // 1000-bit valid bitset
__device__ unsigned            g_colnz[32];      // 1000-bit "column nonzero"
__device__ unsigned            g_mask[K_TOP * 32];
__device__ unsigned            g_barrier;        // starts 0; self-resets
__device__ unsigned            g_work;           // ticket counter; reset in P4

// ---------------- helpers ---------------------------------------------------
__device__ __forceinline__ unsigned f2ord(float f) {
    unsigned u = __float_as_uint(f);
    return (u & 0x80000000u) ? ~u : (u | 0x80000000u);
}
// Sigmoid matching XLA lowering of lax.logistic on GPU (bit-stable vs ref).
__device__ __forceinline__ float ref_sigmoid(float x) {
    float e = expf(-x);
    return __fdiv_rn(1.0f, __fadd_rn(1.0f, e));
}

__device__ __forceinline__ void gridsync(int k) {
    __syncthreads();
    if (threadIdx.x == 0) {
        __threadfence();
        unsigned target = (unsigned)k * GRID;
        unsigned old = atomicAdd(&g_barrier, 1u);
        volatile unsigned* p = &g_barrier;
        if (k == NBAR_FINAL) {
            if (old + 1u == target) {
                atomicExch(&g_barrier, 0u);
            } else {
                while (true) { unsigned v = *p; if (v == 0u || v >= target) break; }
            }
        } else {
            while (*p < target) { }
        }
        __threadfence();
    }
    __syncthreads();
}

// 256-thread find over a 2048-bin global hist: largest bin with
// base_extra + suffix(bin) >= K_TOP. Results in shared vars (all threads see).
__device__ void find_thresh(const unsigned* __restrict__ gh, unsigned base_extra,
                            unsigned* s_bin, unsigned* s_above) {
    __shared__ unsigned ssum[NTHR];
    __shared__ unsigned long long sbest;
    int t = threadIdx.x;
    unsigned h[8];
    unsigned s = 0;
#pragma unroll
    for (int e = 0; e < 8; e++) { h[e] = gh[t * 8 + e]; s += h[e]; }
    ssum[t] = s;
    if (t == 0) sbest = 0ULL;
    __syncthreads();
    for (int off = 1; off < NTHR; off <<= 1) {
        unsigned a = (t + off < NTHR) ? ssum[t + off] : 0u;
        __syncthreads();
        ssum[t] += a;
        __syncthreads();
    }
    unsigned run = ssum[t] - s;
    unsigned long long cand = 0ULL;
#pragma unroll
    for (int e = 7; e >= 0; e--) {
        run += h[e];
        if (base_extra + run >= K_TOP) {
            cand = ((unsigned long long)(t * 8 + e) << 32) | run;
            break;
        }
    }
    if (cand) atomicMax(&sbest, cand);
    __syncthreads();
    if (t == 0) {
        unsigned bin = (unsigned)(sbest >> 32);
        *s_bin = bin;
        if (s_above) *s_above = (unsigned)(sbest & 0xFFFFFFFFu) - gh[bin];
    }
    __syncthreads();
}

// ---------------- the single mega kernel -------------------------------------
__global__ void __launch_bounds__(NTHR, 4)
k_mega(const float* __restrict__ cls, const float* __restrict__ reg,
       const float* __restrict__ anc, float* __restrict__ out) {
    __shared__ unsigned sh[NBINS];
    __shared__ unsigned sB1, sAbove, sBin2, s_chunk;
    const int t = threadIdx.x;
    const int b = blockIdx.x;
    const int warpId = t >> 5;
    const int lane = t & 31;

    // ===== P1: rowmax via dynamic chunk stealing + hist1 ====================
    {
        for (int e = t; e < NBINS; e += NTHR) sh[e] = 0u;
        // zero the small bitsets for this run (writers run in P4/P5)
        if (b == 400 && t < 32) { g_validw[t] = 0u; g_colnz[t] = 0u; }
        const int g = lane >> 2;          // group 0..7 -> row within pass
        const int gl = lane & 3;          // lane within group
        for (;;) {
            __syncthreads();
            if (t == 0) s_chunk = atomicAdd(&g_work, 1u);
            __syncthreads();
            unsigned c = s_chunk;
            if (c >= NCHUNKS) break;
            const int chunkBase = (int)c * CHUNK_ROWS;
#pragma unroll 2
            for (int p = 0; p < 4; p++) {
                int row = chunkBase + p * 64 + warpId * 8 + g;
                const float* rp = cls + (size_t)row * NCLS + gl * 4;
                float4 v0 = *(const float4*)(rp);
                float4 v1 = *(const float4*)(rp + 16);
                float4 v2 = *(const float4*)(rp + 32);
                float4 v3 = *(const float4*)(rp + 48);
                float4 v4 = *(const float4*)(rp + 64);
                float m = fmaxf(fmaxf(v0.x, v0.y), fmaxf(v0.z, v0.w));
                m = fmaxf(m, fmaxf(fmaxf(v1.x, v1.y), fmaxf(v1.z, v1.w)));
                m = fmaxf(m, fmaxf(fmaxf(v2.x, v2.y), fmaxf(v2.z, v2.w)));
                m = fmaxf(m, fmaxf(fmaxf(v3.x, v3.y), fmaxf(v3.z, v3.w)));
                m = fmaxf(m, fmaxf(fmaxf(v4.x, v4.y), fmaxf(v4.z, v4.w)));
                m = fmaxf(m, __shfl_xor_sync(0xffffffffu, m, 1));
                m = fmaxf(m, __shfl_xor_sync(0xffffffffu, m, 2));
                if (gl == 0) {
                    unsigned key = f2ord(ref_sigmoid(m));
                    g_key[row] = key;
                    atomicAdd(&sh[key >> 21], 1u);
                }
            }
        }
        __syncthreads();
        for (int e = t; e < NBINS; e += NTHR) {
            unsigned cc = sh[e];
            if (cc) atomicAdd(&g_hist1[e], cc);
        }
    }
    gridsync(1);

    // ===== P2: all blocks find B1 redundantly; hist2 of bin B1 ==============
    unsigned B1, above;
    {
        find_thresh(g_hist1, 0u, &sB1, &sAbove);
        B1 = sB1; above = sAbove;
        for (int e = t; e < NBINS; e += NTHR) sh[e] = 0u;
        __syncthreads();
        const uint4* kp = (const uint4*)g_key;
        uint4 k4 = kp[b * NTHR + t];
        if ((k4.x >> 21) == B1) atomicAdd(&sh[(k4.x >> 10) & 2047u], 1u);
        if ((k4.y >> 21) == B1) atomicAdd(&sh[(k4.y >> 10) & 2047u], 1u);
        if ((k4.z >> 21) == B1) atomicAdd(&sh[(k4.z >> 10) & 2047u], 1u);
        if ((k4.w >> 21) == B1) atomicAdd(&sh[(k4.w >> 10) & 2047u], 1u);
        __syncthreads();
        for (int e = t; e < NBINS; e += NTHR) {
            unsigned c = sh[e];
            if (c) atomicAdd(&g_hist2[e], c);
        }
    }
    gridsync(2);

    // ===== P3: all blocks find refined threshold; compact ===================
    {
        find_thresh(g_hist2, above, &sBin2, 0);
        unsigned thr = (B1 << 21) | (sBin2 << 10);
        const uint4* kp = (const uint4*)g_key;
        int i4 = b * NTHR + t;
        uint4 k4 = kp[i4];
        int i0 = i4 * 4;
        unsigned keys[4] = { k4.x, k4.y, k4.z, k4.w };
#pragma unroll
        for (int c = 0; c < 4; c++) {
            bool f = keys[c] >= thr;
            unsigned bal = __ballot_sync(0xffffffffu, f);
            if (bal) {
                unsigned base;
                if (lane == 0) base = atomicAdd(&g_candCount, (unsigned)__popc(bal));
                base = __shfl_sync(0xffffffffu, base, 0);
                if (f) {
                    unsigned pos = base + __popc(bal & ((1u << lane) - 1u));
                    if (pos < CAND_CAP)
                        g_cand[pos] = ((unsigned long long)keys[c] << 32) |
                                      (unsigned)(~(i0 + c));
                }
            }
        }
    }
    gridsync(3);

    // ===== P4: rank + decode fused; idle blocks do scratch cleanup ==========
    {
        unsigned cnt = min(g_candCount, (unsigned)CAND_CAP);
        unsigned id = b * NTHR + t;
        if ((unsigned)(b * NTHR) < cnt) {
            unsigned long long my = (id < cnt) ? g_cand[id] : 0ULL;
            unsigned rank = 0, jj = 0;
            for (; jj + 4 <= cnt; jj += 4) {
                unsigned long long a0 = g_cand[jj],     a1 = g_cand[jj + 1];
                unsigned long long a2 = g_cand[jj + 2], a3 = g_cand[jj + 3];
                rank += (a0 > my) + (a1 > my) + (a2 > my) + (a3 > my);
            }
            for (; jj < cnt; jj++) rank += (g_cand[jj] > my);
            if (id < cnt && rank < K_TOP) {
                int i = (int)(~(unsigned)(my & 0xFFFFFFFFULL));
                int j = (int)rank;
                const float4* row = (const float4*)(cls + (size_t)i * NCLS);
                float best = -1.0f; int bl = 0;
#pragma unroll
                for (int q = 0; q < NCLS / 4; q++) {
                    float4 v = row[q];
                    float s0 = ref_sigmoid(v.x), s1 = ref_sigmoid(v.y);
                    float s2 = ref_sigmoid(v.z), s3 = ref_sigmoid(v.w);
                    if (s0 > best) { best = s0; bl = 4 * q + 0; }
                    if (s1 > best) { best = s1; bl = 4 * q + 1; }
                    if (s2 > best) { best = s2; bl = 4 * q + 2; }
                    if (s3 > best) { best = s3; bl = 4 * q + 3; }
                }
                float4 rg = ((const float4*)reg)[i];
                float4 an = ((const float4*)anc)[i];
                float ox = fminf(fmaxf(rg.x * an.z, -32.0f), 32.0f);
                float oy = fminf(fmaxf(rg.y * an.w, -32.0f), 32.0f);
                float cx = an.x + ox, cy = an.y + oy;
                float w = an.z * expf(fminf(rg.z, SCALE_CLAMP));
                float h = an.w * expf(fminf(rg.w, SCALE_CLAMP));
                float x1 = fminf(fmaxf((cx - 0.5f * w) * IMG_INV, 0.0f), 1.0f);
                float y1 = fminf(fmaxf((cy - 0.5f * h) * IMG_INV, 0.0f), 1.0f);
                float x2 = fminf(fmaxf((cx + 0.5f * w) * IMG_INV, 0.0f), 1.0f);
                float y2 = fminf(fmaxf((cy + 0.5f * h) * IMG_INV, 0.0f), 1.0f);
                out[4 * j + 0] = x1; out[4 * j + 1] = y1;
                out[4 * j + 2] = x2; out[4 * j + 3] = y2;
                out[4000 + j] = best;
                out[5000 + j] = (float)bl;
                g_boxes[j] = make_float4(x1, y1, x2, y2);
                g_labels[j] = bl;
                if (best >= 0.05f)
                    atomicOr(&g_validw[j >> 5], 1u << (j & 31));
            }
        }
        // cleanup for next run (graph replay): hists + work ticket
        if (b >= 560 && b < 568) g_hist1[(b - 560) * NTHR + t] = 0u;
        if (b >= 568 && b < 576) g_hist2[(b - 568) * NTHR + t] = 0u;
        if (b == 5 && t == 0) g_work = 0u;
    }
    gridsync(4);

    // ===== P5: suppression bitmask + column-nonzero bitset ==================
    {
        int gw = b * (NTHR / 32) + warpId;
        for (int task = gw; task < K_TOP * 32; task += GRID * (NTHR / 32)) {
            int i = task >> 5, W = task & 31;
            float4 bi = g_boxes[i];
            int li = g_labels[i];
            float ai = (bi.z - bi.x) * (bi.w - bi.y);
            int j = W * 32 + lane;
            bool sup = false;
            if (j < i && g_labels[j] == li) {
                float4 bj = g_boxes[j];
                float xx1 = fmaxf(bi.x, bj.x), yy1 = fmaxf(bi.y, bj.y);
                float xx2 = fminf(bi.z, bj.z), yy2 = fminf(bi.w, bj.w);
                float ww = fmaxf(1e-10f, xx2 - xx1);
                float hh = fmaxf(1e-10f, yy2 - yy1);
                float inter = ww * hh;
                float aj = (bj.z - bj.x) * (bj.w - bj.y);
                float iou = inter / (ai + aj - inter + 1e-10f);
                sup = iou > 0.6f;
            }
            unsigned bits = __ballot_sync(0xffffffffu, sup);
            if (lane == 0) {
                g_mask[task] = bits;
                if (bits) atomicOr(&g_colnz[i >> 5], 1u << (i & 31));
            }
        }
        if (b == 5 && t == 0) g_candCount = 0u;
    }
    gridsync(5);   // FINAL: self-resets g_barrier

    // ===== P6: block0 sparse greedy NMS =====================================
    if (b == 0 && t < 32) {
        unsigned vw = g_validw[t];
        unsigned cz = g_colnz[t];
        unsigned kw = vw & ~cz;            // zero-column candidates: keep=valid
        for (int w = 0; w < 32; w++) {
            unsigned word  = __shfl_sync(0xffffffffu, cz, w);
            unsigned vword = __shfl_sync(0xffffffffu, vw, w);
            while (word) {
                int bbit = __ffs(word) - 1;
                word &= word - 1u;
                int i = w * 32 + bbit;
                unsigned colw = g_mask[i * 32 + t];
                bool ov = __any_sync(0xffffffffu, (colw & kw) != 0u);
                bool kp = ((vword >> bbit) & 1u) && !ov;
                if (kp && t == w) kw |= (1u << bbit);
            }
        }
#pragma unroll
        for (int e = 0; e < 32; e++) {
            int i = t * 32 + e;
            if (i < K_TOP) out[6000 + i] = ((kw >> e) & 1u) ? 1.0f : 0.0f;
        }
    }
}

// ---------------- launcher ---------------------------------------------------
extern "C" void kernel_launch(void* const* d_in, const int* in_sizes, int n_in,
                              void* d_out, int out_size) {
    const float* cls = (const float*)d_in[0];
    const float* reg = (const float*)d_in[1];
    const float* anc = (const float*)d_in[2];
    float* out = (float*)d_out;
    (void)in_sizes; (void)n_in; (void)out_size;

    k_mega<<<GRID, NTHR>>>(cls, reg, anc, out);
}

// round 8
// speedup vs baseline: 1.0003x; 1.0003x over previous
#include <cuda_runtime.h>
#include <math.h>

#define M_ANCH   589824
#define NCLS     80
#define K_TOP    1000
#define CAND_CAP 4096
#define NBINS    2048
#define GRID     576
#define NTHR     256
#define NBAR_FINAL 4
#define IMG_INV  (1.0f/2048.0f)
#define SCALE_CLAMP 4.1351665567423560f   /* log(1000/16) */

// ---------------- scratch (device globals; no allocations allowed) ----------
__device__ unsigned            g_key[M_ANCH];
__device__ unsigned            g_hist1[NBINS];
__device__ unsigned            g_hist2[NBINS];
__device__ unsigned            g_candCount;
__device__ unsigned long long  g_cand[CAND_CAP];
__device__ float4              g_boxes[K_TOP];
__device__ int                 g_labels[K_TOP];
__device__ unsigned            g_validw[32];     // 1000-bit valid bitset
__device__ unsigned            g_colnz[32];      // 1000-bit "column nonzero"
__device__ unsigned            g_mask[K_TOP * 32];
__device__ unsigned            g_barrier;        // starts 0; self-resets

// ---------------- helpers ---------------------------------------------------
__device__ __forceinline__ unsigned f2ord(float f) {
    unsigned u = __float_as_uint(f);
    return (u & 0x80000000u) ? ~u : (u | 0x80000000u);
}
// Sigmoid matching XLA lowering of lax.logistic on GPU (bit-stable vs ref).
__device__ __forceinline__ float ref_sigmoid(float x) {
    float e = expf(-x);
    return __fdiv_rn(1.0f, __fadd_rn(1.0f, e));
}

__device__ __forceinline__ void gridsync(int k) {
    __syncthreads();
    if (threadIdx.x == 0) {
        __threadfence();
        unsigned target = (unsigned)k * GRID;
        unsigned old = atomicAdd(&g_barrier, 1u);
        volatile unsigned* p = &g_barrier;
        if (k == NBAR_FINAL) {
            if (old + 1u == target) {
                atomicExch(&g_barrier, 0u);
            } else {
                while (true) { unsigned v = *p; if (v == 0u || v >= target) break; }
            }
        } else {
            while (*p < target) { }
        }
        __threadfence();
    }
    __syncthreads();
}

// 256-thread find over a 2048-bin global hist: largest bin with
// base_extra + suffix(bin) >= K_TOP. Results in shared vars (all threads see).
__device__ void find_thresh(const unsigned* __restrict__ gh, unsigned base_extra,
                            unsigned* s_bin, unsigned* s_above) {
    __shared__ unsigned ssum[NTHR];
    __shared__ unsigned long long sbest;
    int t = threadIdx.x;
    unsigned h[8];
    unsigned s = 0;
#pragma unroll
    for (int e = 0; e < 8; e++) { h[e] = gh[t * 8 + e]; s += h[e]; }
    ssum[t] = s;
    if (t == 0) sbest = 0ULL;
    __syncthreads();
    for (int off = 1; off < NTHR; off <<= 1) {
        unsigned a = (t + off < NTHR) ? ssum[t + off] : 0u;
        __syncthreads();
        ssum[t] += a;
        __syncthreads();
    }
    unsigned run = ssum[t] - s;
    unsigned long long cand = 0ULL;
#pragma unroll
    for (int e = 7; e >= 0; e--) {
        run += h[e];
        if (base_extra + run >= K_TOP) {
            cand = ((unsigned long long)(t * 8 + e) << 32) | run;
            break;
        }
    }
    if (cand) atomicMax(&sbest, cand);
    __syncthreads();
    if (t == 0) {
        unsigned bin = (unsigned)(sbest >> 32);
        *s_bin = bin;
        if (s_above) *s_above = (unsigned)(sbest & 0xFFFFFFFFu) - gh[bin];
    }
    __syncthreads();
}

// ---------------- kernel 1: rowmax + hist1, software-pipelined ---------------
__global__ void __launch_bounds__(NTHR, 4)
k_p1(const float* __restrict__ cls) {
    __shared__ unsigned sh[NBINS];
    const int t = threadIdx.x;
    const int b = blockIdx.x;
    const int warpId = t >> 5;
    const int lane = t & 31;
    const int g = lane >> 2;          // group 0..7 -> row within pass
    const int gl = lane & 3;          // lane within group

    for (int e = t; e < NBINS; e += NTHR) sh[e] = 0u;
    __syncthreads();

    // block covers rows [b*1024, b*1024+1024); warp covers 128 of them,
    // 8 rows per pass, 16 passes, double-buffered (prefetch next pass).
    const int rowBase = b * 1024 + warpId * 128 + g;
    const float* basep = cls + (size_t)rowBase * NCLS + gl * 4;

    float4 A0, A1, A2, A3, A4;
    {
        const float* rp = basep;
        A0 = *(const float4*)(rp);
        A1 = *(const float4*)(rp + 16);
        A2 = *(const float4*)(rp + 32);
        A3 = *(const float4*)(rp + 48);
        A4 = *(const float4*)(rp + 64);
    }
#pragma unroll 2
    for (int p = 0; p < 16; p++) {
        // prefetch next pass (clamped re-load of last pass at the end)
        int pn = (p < 15) ? p + 1 : 15;
        const float* rp = basep + (size_t)pn * 8 * NCLS;
        float4 B0 = *(const float4*)(rp);
        float4 B1 = *(const float4*)(rp + 16);
        float4 B2 = *(const float4*)(rp + 32);
        float4 B3 = *(const float4*)(rp + 48);
        float4 B4 = *(const float4*)(rp + 64);

        float m = fmaxf(fmaxf(A0.x, A0.y), fmaxf(A0.z, A0.w));
        m = fmaxf(m, fmaxf(fmaxf(A1.x, A1.y), fmaxf(A1.z, A1.w)));
        m = fmaxf(m, fmaxf(fmaxf(A2.x, A2.y), fmaxf(A2.z, A2.w)));
        m = fmaxf(m, fmaxf(fmaxf(A3.x, A3.y), fmaxf(A3.z, A3.w)));
        m = fmaxf(m, fmaxf(fmaxf(A4.x, A4.y), fmaxf(A4.z, A4.w)));
        m = fmaxf(m, __shfl_xor_sync(0xffffffffu, m, 1));
        m = fmaxf(m, __shfl_xor_sync(0xffffffffu, m, 2));
        if (gl == 0) {
            unsigned key = f2ord(ref_sigmoid(m));
            g_key[rowBase + p * 8] = key;
            atomicAdd(&sh[key >> 21], 1u);
        }
        A0 = B0; A1 = B1; A2 = B2; A3 = B3; A4 = B4;
    }
    __syncthreads();
    for (int e = t; e < NBINS; e += NTHR) {
        unsigned c = sh[e];
        if (c) atomicAdd(&g_hist1[e], c);
    }
}

// ---------------- kernel 2: phases 2-6 ---------------------------------------
__global__ void __launch_bounds__(NTHR, 4)
k_rest(const float* __restrict__ cls, const float* __restrict__ reg,
       const float* __restrict__ anc, float* __restrict__ out) {
    __shared__ unsigned sh[NBINS];
    __shared__ unsigned sB1, sAbove, sBin2;
    const int t = threadIdx.x;
    const int b = blockIdx.x;
    const int warpId = t >> 5;
    const int lane = t & 31;

    // ===== R1: all blocks find B1 redundantly; hist2 of bin B1 ==============
    unsigned B1, above;
    {
        if (b == 400 && t < 32) { g_validw[t] = 0u; g_colnz[t] = 0u; }
        find_thresh(g_hist1, 0u, &sB1, &sAbove);
        B1 = sB1; above = sAbove;
        for (int e = t; e < NBINS; e += NTHR) sh[e] = 0u;
        __syncthreads();
        const uint4* kp = (const uint4*)g_key;
        uint4 k4 = kp[b * NTHR + t];
        if ((k4.x >> 21) == B1) atomicAdd(&sh[(k4.x >> 10) & 2047u], 1u);
        if ((k4.y >> 21) == B1) atomicAdd(&sh[(k4.y >> 10) & 2047u], 1u);
        if ((k4.z >> 21) == B1) atomicAdd(&sh[(k4.z >> 10) & 2047u], 1u);
        if ((k4.w >> 21) == B1) atomicAdd(&sh[(k4.w >> 10) & 2047u], 1u);
        __syncthreads();
        for (int e = t; e < NBINS; e += NTHR) {
            unsigned c = sh[e];
            if (c) atomicAdd(&g_hist2[e], c);
        }
    }
    gridsync(1);

    // ===== R2: all blocks find refined threshold; compact ===================
    {
        find_thresh(g_hist2, above, &sBin2, 0);
        unsigned thr = (B1 << 21) | (sBin2 << 10);
        const uint4* kp = (const uint4*)g_key;
        int i4 = b * NTHR + t;
        uint4 k4 = kp[i4];
        int i0 = i4 * 4;
        unsigned keys[4] = { k4.x, k4.y, k4.z, k4.w };
#pragma unroll
        for (int c = 0; c < 4; c++) {
            bool f = keys[c] >= thr;
            unsigned bal = __ballot_sync(0xffffffffu, f);
            if (bal) {
                unsigned base;
                if (lane == 0) base = atomicAdd(&g_candCount, (unsigned)__popc(bal));
                base = __shfl_sync(0xffffffffu, base, 0);
                if (f) {
                    unsigned pos = base + __popc(bal & ((1u << lane) - 1u));
                    if (pos < CAND_CAP)
                        g_cand[pos] = ((unsigned long long)keys[c] << 32) |
                                      (unsigned)(~(i0 + c));
                }
            }
        }
    }
    gridsync(2);

    // ===== R3: rank + decode fused; idle blocks zero histograms =============
    {
        unsigned cnt = min(g_candCount, (unsigned)CAND_CAP);
        unsigned id = b * NTHR + t;
        if ((unsigned)(b * NTHR) < cnt) {
            unsigned long long my = (id < cnt) ? g_cand[id] : 0ULL;
            unsigned rank = 0, jj = 0;
            for (; jj + 4 <= cnt; jj += 4) {
                unsigned long long a0 = g_cand[jj],     a1 = g_cand[jj + 1];
                unsigned long long a2 = g_cand[jj + 2], a3 = g_cand[jj + 3];
                rank += (a0 > my) + (a1 > my) + (a2 > my) + (a3 > my);
            }
            for (; jj < cnt; jj++) rank += (g_cand[jj] > my);
            if (id < cnt && rank < K_TOP) {
                int i = (int)(~(unsigned)(my & 0xFFFFFFFFULL));
                int j = (int)rank;
                const float4* row = (const float4*)(cls + (size_t)i * NCLS);
                float best = -1.0f; int bl = 0;
#pragma unroll
                for (int q = 0; q < NCLS / 4; q++) {
                    float4 v = row[q];
                    float s0 = ref_sigmoid(v.x), s1 = ref_sigmoid(v.y);
                    float s2 = ref_sigmoid(v.z), s3 = ref_sigmoid(v.w);
                    if (s0 > best) { best = s0; bl = 4 * q + 0; }
                    if (s1 > best) { best = s1; bl = 4 * q + 1; }
                    if (s2 > best) { best = s2; bl = 4 * q + 2; }
                    if (s3 > best) { best = s3; bl = 4 * q + 3; }
                }
                float4 rg = ((const float4*)reg)[i];
                float4 an = ((const float4*)anc)[i];
                float ox = fminf(fmaxf(rg.x * an.z, -32.0f), 32.0f);
                float oy = fminf(fmaxf(rg.y * an.w, -32.0f), 32.0f);
                float cx = an.x + ox, cy = an.y + oy;
                float w = an.z * expf(fminf(rg.z, SCALE_CLAMP));
                float h = an.w * expf(fminf(rg.w, SCALE_CLAMP));
                float x1 = fminf(fmaxf((cx - 0.5f * w) * IMG_INV, 0.0f), 1.0f);
                float y1 = fminf(fmaxf((cy - 0.5f * h) * IMG_INV, 0.0f), 1.0f);
                float x2 = fminf(fmaxf((cx + 0.5f * w) * IMG_INV, 0.0f), 1.0f);
                float y2 = fminf(fmaxf((cy + 0.5f * h) * IMG_INV, 0.0f), 1.0f);
                out[4 * j + 0] = x1; out[4 * j + 1] = y1;
                out[4 * j + 2] = x2; out[4 * j + 3] = y2;
                out[4000 + j] = best;
                out[5000 + j] = (float)bl;
                g_boxes[j] = make_float4(x1, y1, x2, y2);
                g_labels[j] = bl;
                if (best >= 0.05f)
                    atomicOr(&g_validw[j >> 5], 1u << (j & 31));
            }
        }
        // cleanup for next run (graph replay)
        if (b >= 560 && b < 568) g_hist1[(b - 560) * NTHR + t] = 0u;
        if (b >= 568 && b < 576) g_hist2[(b - 568) * NTHR + t] = 0u;
    }
    gridsync(3);

    // ===== R4: suppression bitmask + column-nonzero bitset ==================
    {
        int gw = b * (NTHR / 32) + warpId;
        for (int task = gw; task < K_TOP * 32; task += GRID * (NTHR / 32)) {
            int i = task >> 5, W = task & 31;
            float4 bi = g_boxes[i];
            int li = g_labels[i];
            float ai = (bi.z - bi.x) * (bi.w - bi.y);
            int j = W * 32 + lane;
            bool sup = false;
            if (j < i && g_labels[j] == li) {
                float4 bj = g_boxes[j];
                float xx1 = fmaxf(bi.x, bj.x), yy1 = fmaxf(bi.y, bj.y);
                float xx2 = fminf(bi.z, bj.z), yy2 = fminf(bi.w, bj.w);
                float ww = fmaxf(1e-10f, xx2 - xx1);
                float hh = fmaxf(1e-10f, yy2 - yy1);
                float inter = ww * hh;
                float aj = (bj.z - bj.x) * (bj.w - bj.y);
                float iou = inter / (ai + aj - inter + 1e-10f);
                sup = iou > 0.6f;
            }
            unsigned bits = __ballot_sync(0xffffffffu, sup);
            if (lane == 0) {
                g_mask[task] = bits;
                if (bits) atomicOr(&g_colnz[i >> 5], 1u << (i & 31));
            }
        }
        if (b == 5 && t == 0) g_candCount = 0u;
    }
    gridsync(4);   // FINAL: self-resets g_barrier

    // ===== R5: block0 sparse greedy NMS =====================================
    if (b == 0 && t < 32) {
        unsigned vw = g_validw[t];
        unsigned cz = g_colnz[t];
        unsigned kw = vw & ~cz;            // zero-column candidates: keep=valid
        for (int w = 0; w < 32; w++) {
            unsigned word  = __shfl_sync(0xffffffffu, cz, w);
            unsigned vword = __shfl_sync(0xffffffffu, vw, w);
            while (word) {
                int bbit = __ffs(word) - 1;
                word &= word - 1u;
                int i = w * 32 + bbit;
                unsigned colw = g_mask[i * 32 + t];
                bool ov = __any_sync(0xffffffffu, (colw & kw) != 0u);
                bool kp = ((vword >> bbit) & 1u) && !ov;
                if (kp && t == w) kw |= (1u << bbit);
            }
        }
#pragma unroll
        for (int e = 0; e < 32; e++) {
            int i = t * 32 + e;
            if (i < K_TOP) out[6000 + i] = ((kw >> e) & 1u) ? 1.0f : 0.0f;
        }
    }
}

// ---------------- launcher ---------------------------------------------------
extern "C" void kernel_launch(void* const* d_in, const int* in_sizes, int n_in,
                              void* d_out, int out_size) {
    const float* cls = (const float*)d_in[0];
    const float* reg = (const float*)d_in[1];
    const float* anc = (const float*)d_in[2];
    float* out = (float*)d_out;
    (void)in_sizes; (void)n_in; (void)out_size;

    k_p1<<<GRID, NTHR>>>(cls);
    k_rest<<<GRID, NTHR>>>(cls, reg, anc, out);
}